// round 3
// baseline (speedup 1.0000x reference)
#include <cuda_runtime.h>

typedef unsigned long long u64;

#define NT 896
#define BT 56
#define RS 58          /* u64 row stride (even -> 16B-aligned LDS.128) */
#define B_TOT 8192
#define T_STEPS 30
#define WARM 24

__device__ __forceinline__ u64 pack2(float lo, float hi){
    u64 r; asm("mov.b64 %0, {%1, %2};" : "=l"(r) : "f"(lo), "f"(hi)); return r;
}
__device__ __forceinline__ void unpack2(u64 v, float& lo, float& hi){
    asm("mov.b64 {%0, %1}, %2;" : "=f"(lo), "=f"(hi) : "l"(v));
}
__device__ __forceinline__ u64 fma2(u64 a, u64 b, u64 c){
    u64 d; asm("fma.rn.f32x2 %0, %1, %2, %3;" : "=l"(d) : "l"(a), "l"(b), "l"(c)); return d;
}
__device__ __forceinline__ float sig_(float x){ return __fdividef(1.f, 1.f + __expf(-x)); }
__device__ __forceinline__ float tanh_(float x){ return 1.f - 2.f * __fdividef(1.f, __expf(2.f * x) + 1.f); }

// smem: hdup[136][RS] u64, m1dup[128][RS] u64, then floats: cbz512 cb1 cb2 cwo (128 ea), red 112, predb 56
#define SMEM_BYTES ((136 + 128) * RS * 8 + (512 + 128 + 128 + 128 + 112 + 56) * 4)

__global__ void __launch_bounds__(NT, 1)
fused_lstm_kernel(const float* __restrict__ x0, const float* __restrict__ x1,
                  const float* __restrict__ x2, const float* __restrict__ x3,
                  const float* __restrict__ x4, const float* __restrict__ x5,
                  const float* __restrict__ x6, const float* __restrict__ irr,
                  const float* __restrict__ Wi, const float* __restrict__ Wh,
                  const float* __restrict__ bz, const float* __restrict__ W1,
                  const float* __restrict__ b1, const float* __restrict__ W2,
                  const float* __restrict__ b2, const float* __restrict__ Wout,
                  const float* __restrict__ bout, float* __restrict__ out)
{
    extern __shared__ u64 sm[];
    u64* hdup  = sm;                 // [136][RS]  rows 0-127: h dup; 128-135: inputs dup
    u64* m1dup = sm + 136 * RS;      // [128][RS]
    float* fs    = (float*)(sm + 264 * RS);
    float* cbz   = fs;               // 512
    float* cb1   = cbz + 512;        // 128
    float* cb2   = cb1 + 128;        // 128
    float* cwo   = cb2 + 128;        // 128
    float* red   = cwo + 128;        // 2*BT
    float* predb = red + 2 * BT;     // BT

    const int tid = threadIdx.x;
    const int cg  = tid & 63;        // 64 col-groups (2 channels each)
    const int rg  = tid >> 6;        // 0..13 row-groups (4 rows each)
    const int r0  = rg << 2;
    const int ch0 = cg << 1;
    const int b0  = blockIdx.x * BT;

    for (int i = tid; i < 128 * RS; i += NT) hdup[i] = 0ull;
    for (int i = tid; i < 512; i += NT) cbz[i] = bz[i];
    if (tid < 128){ cb1[tid] = b1[tid]; cb2[tid] = b2[tid]; cwo[tid] = Wout[tid]; }
    const float boutv = bout[0];
    const float wo0 = Wout[ch0], wo1 = Wout[ch0 + 1];

    const int lf = tid / BT, lr = tid - lf * BT;   // valid when tid < 448
    const float* fptr = x0; int tmax = 0;
    if (tid < 8 * BT){
        int lb = b0 + lr; if (lb > B_TOT - 1) lb = B_TOT - 1;
        const float* p;
        if      (lf == 0) p = x0; else if (lf == 1) p = x1;
        else if (lf == 2) p = x2; else if (lf == 3) p = x3;
        else if (lf == 4) p = x4; else if (lf == 5) p = x5;
        else if (lf == 6) p = x6; else              p = irr;
        fptr = (lf < 7) ? (p + lb * T_STEPS) : (p + lb * WARM);
        tmax = (lf < 7) ? (T_STEPS - 1) : (WARM - 1);
    }

    u64 cst[4] = {0ull, 0ull, 0ull, 0ull};
    __syncthreads();

    for (int t = 0; t < T_STEPS; ++t){
        if (tid < 8 * BT){
            int ti = t < tmax ? t : tmax;
            float gv = __ldg(fptr + ti);
            float v = (lf < 7 || t < WARM) ? gv : predb[lr];
            hdup[(128 + lf) * RS + lr] = pack2(v, v);
        }
        __syncthreads();

        // ---- z = [h, inp] @ [Wh; Wi] + b : acc[row j][gate q] packs cols (ch0, ch0+1)
        u64 acc[4][4];
        #pragma unroll
        for (int q = 0; q < 4; q++){
            u64 bq = *reinterpret_cast<const u64*>(&cbz[(q << 7) + ch0]);
            acc[0][q] = bq; acc[1][q] = bq; acc[2][q] = bq; acc[3][q] = bq;
        }
        {
            const float* wr = Wh + ch0;
            #pragma unroll 2
            for (int k = 0; k < 128; k++){
                const u64* hp = hdup + k * RS + r0;
                ulonglong2 ha = *reinterpret_cast<const ulonglong2*>(hp);
                ulonglong2 hb = *reinterpret_cast<const ulonglong2*>(hp + 2);
                #pragma unroll
                for (int q = 0; q < 4; q++){
                    u64 wp = *reinterpret_cast<const u64*>(wr + (q << 7));
                    acc[0][q] = fma2(ha.x, wp, acc[0][q]);
                    acc[1][q] = fma2(ha.y, wp, acc[1][q]);
                    acc[2][q] = fma2(hb.x, wp, acc[2][q]);
                    acc[3][q] = fma2(hb.y, wp, acc[3][q]);
                }
                wr += 512;
            }
            const float* wi = Wi + ch0;
            #pragma unroll 2
            for (int f = 0; f < 8; f++){
                const u64* hp = hdup + (128 + f) * RS + r0;
                ulonglong2 ha = *reinterpret_cast<const ulonglong2*>(hp);
                ulonglong2 hb = *reinterpret_cast<const ulonglong2*>(hp + 2);
                #pragma unroll
                for (int q = 0; q < 4; q++){
                    u64 wp = *reinterpret_cast<const u64*>(wi + (q << 7));
                    acc[0][q] = fma2(ha.x, wp, acc[0][q]);
                    acc[1][q] = fma2(ha.y, wp, acc[1][q]);
                    acc[2][q] = fma2(hb.x, wp, acc[2][q]);
                    acc[3][q] = fma2(hb.y, wp, acc[3][q]);
                }
                wi += 512;
            }
        }
        __syncthreads();   // all reads of h-region done before overwrite

        // ---- gates; c in regs; write h duplicated, k-major
        #pragma unroll
        for (int j = 0; j < 4; j++){
            float zi0,zi1,zf0,zf1,zg0,zg1,zo0,zo1,c0,c1;
            unpack2(acc[j][0], zi0, zi1);
            unpack2(acc[j][1], zf0, zf1);
            unpack2(acc[j][2], zg0, zg1);
            unpack2(acc[j][3], zo0, zo1);
            unpack2(cst[j], c0, c1);
            c0 = sig_(zf0) * c0 + sig_(zi0) * tanh_(zg0);
            c1 = sig_(zf1) * c1 + sig_(zi1) * tanh_(zg1);
            cst[j] = pack2(c0, c1);
            float h0 = sig_(zo0) * tanh_(c0);
            float h1 = sig_(zo1) * tanh_(c1);
            hdup[ ch0      * RS + r0 + j] = pack2(h0, h0);
            hdup[(ch0 + 1) * RS + r0 + j] = pack2(h1, h1);
        }
        __syncthreads();

        // ---- m1 = relu(h @ W1 + b1)
        u64 a1[4];
        { u64 bq = *reinterpret_cast<const u64*>(&cb1[ch0]);
          a1[0] = bq; a1[1] = bq; a1[2] = bq; a1[3] = bq; }
        {
            const float* wr = W1 + ch0;
            #pragma unroll 2
            for (int k = 0; k < 128; k++){
                const u64* hp = hdup + k * RS + r0;
                ulonglong2 ha = *reinterpret_cast<const ulonglong2*>(hp);
                ulonglong2 hb = *reinterpret_cast<const ulonglong2*>(hp + 2);
                u64 wp = *reinterpret_cast<const u64*>(wr);
                a1[0] = fma2(ha.x, wp, a1[0]);
                a1[1] = fma2(ha.y, wp, a1[1]);
                a1[2] = fma2(hb.x, wp, a1[2]);
                a1[3] = fma2(hb.y, wp, a1[3]);
                wr += 128;
            }
        }
        #pragma unroll
        for (int j = 0; j < 4; j++){
            float v0, v1; unpack2(a1[j], v0, v1);
            v0 = fmaxf(v0, 0.f); v1 = fmaxf(v1, 0.f);
            m1dup[ ch0      * RS + r0 + j] = pack2(v0, v0);
            m1dup[(ch0 + 1) * RS + r0 + j] = pack2(v1, v1);
        }
        __syncthreads();

        // ---- m2 = relu(m1 @ W2 + b2), out-proj fused in registers
        u64 a2[4];
        { u64 bq = *reinterpret_cast<const u64*>(&cb2[ch0]);
          a2[0] = bq; a2[1] = bq; a2[2] = bq; a2[3] = bq; }
        {
            const float* wr = W2 + ch0;
            #pragma unroll 2
            for (int k = 0; k < 128; k++){
                const u64* hp = m1dup + k * RS + r0;
                ulonglong2 ha = *reinterpret_cast<const ulonglong2*>(hp);
                ulonglong2 hb = *reinterpret_cast<const ulonglong2*>(hp + 2);
                u64 wp = *reinterpret_cast<const u64*>(wr);
                a2[0] = fma2(ha.x, wp, a2[0]);
                a2[1] = fma2(ha.y, wp, a2[1]);
                a2[2] = fma2(hb.x, wp, a2[2]);
                a2[3] = fma2(hb.y, wp, a2[3]);
                wr += 128;
            }
        }
        float part[4];
        #pragma unroll
        for (int j = 0; j < 4; j++){
            float v0, v1; unpack2(a2[j], v0, v1);
            part[j] = fmaxf(v0, 0.f) * wo0 + fmaxf(v1, 0.f) * wo1;
        }
        #pragma unroll
        for (int off = 16; off; off >>= 1){
            part[0] += __shfl_xor_sync(0xffffffffu, part[0], off);
            part[1] += __shfl_xor_sync(0xffffffffu, part[1], off);
            part[2] += __shfl_xor_sync(0xffffffffu, part[2], off);
            part[3] += __shfl_xor_sync(0xffffffffu, part[3], off);
        }
        if ((tid & 31) == 0){
            int half = (tid >> 5) & 1;
            red[half * BT + r0 + 0] = part[0];
            red[half * BT + r0 + 1] = part[1];
            red[half * BT + r0 + 2] = part[2];
            red[half * BT + r0 + 3] = part[3];
        }
        __syncthreads();
        if (tid < BT){
            float s = boutv + red[tid] + red[BT + tid];
            predb[tid] = s;
            int bb = b0 + tid;
            if (bb < B_TOT) out[bb * T_STEPS + t] = s;
        }
        __syncthreads();
    }
}

extern "C" void kernel_launch(void* const* d_in, const int* in_sizes, int n_in,
                              void* d_out, int out_size)
{
    (void)in_sizes; (void)n_in; (void)out_size;
    cudaFuncSetAttribute(fused_lstm_kernel, cudaFuncAttributeMaxDynamicSharedMemorySize, SMEM_BYTES);
    int grid = (B_TOT + BT - 1) / BT; // 147
    fused_lstm_kernel<<<grid, NT, SMEM_BYTES>>>(
        (const float*)d_in[8],  (const float*)d_in[9],  (const float*)d_in[10],
        (const float*)d_in[11], (const float*)d_in[12], (const float*)d_in[13],
        (const float*)d_in[14], (const float*)d_in[15],
        (const float*)d_in[16], (const float*)d_in[17], (const float*)d_in[18],
        (const float*)d_in[19], (const float*)d_in[20], (const float*)d_in[21],
        (const float*)d_in[22], (const float*)d_in[23], (const float*)d_in[24],
        (float*)d_out);
}

// round 4
// speedup vs baseline: 1.4149x; 1.4149x over previous
#include <cuda_runtime.h>

typedef unsigned long long u64;

#define NT 448
#define BT 56
#define RSTR 58
#define B_TOT 8192
#define T_STEPS 30
#define WARM 24

__device__ __forceinline__ u64 pack2(float lo, float hi){
    u64 r; asm("mov.b64 %0, {%1, %2};" : "=l"(r) : "f"(lo), "f"(hi)); return r;
}
__device__ __forceinline__ void unpack2(u64 v, float& lo, float& hi){
    asm("mov.b64 {%0, %1}, %2;" : "=f"(lo), "=f"(hi) : "l"(v));
}
__device__ __forceinline__ u64 fma2(u64 a, u64 b, u64 c){
    u64 d; asm("fma.rn.f32x2 %0, %1, %2, %3;" : "=l"(d) : "l"(a), "l"(b), "l"(c)); return d;
}
__device__ __forceinline__ float sig_(float x){ return __fdividef(1.f, 1.f + __expf(-x)); }
__device__ __forceinline__ float tanh_(float x){ return 1.f - 2.f * __fdividef(1.f, __expf(2.f * x) + 1.f); }

// smem floats: hbuf 136*58 + m1buf 128*58 + wbuf 2*4096 + red 112 + predb 56
#define SMEM_FLOATS (136*RSTR + 128*RSTR + 8192 + 2*BT + BT)
#define SMEM_BYTES (SMEM_FLOATS * 4)

__global__ void __launch_bounds__(NT, 1)
fused_lstm_kernel(const float* __restrict__ x0, const float* __restrict__ x1,
                  const float* __restrict__ x2, const float* __restrict__ x3,
                  const float* __restrict__ x4, const float* __restrict__ x5,
                  const float* __restrict__ x6, const float* __restrict__ irr,
                  const float* __restrict__ Wi, const float* __restrict__ Wh,
                  const float* __restrict__ bz, const float* __restrict__ W1,
                  const float* __restrict__ b1, const float* __restrict__ W2,
                  const float* __restrict__ b2, const float* __restrict__ Wout,
                  const float* __restrict__ bout, float* __restrict__ out)
{
    extern __shared__ float smem[];
    float* hbuf  = smem;                  // [136][58]: rows 0-127 h (unit-major), 128-135 inputs
    float* m1buf = hbuf  + 136 * RSTR;    // [128][58]
    float* wsm   = m1buf + 128 * RSTR;    // 2 x 4096 staging buffers
    float* red   = wsm   + 8192;          // [2][56]
    float* predb = red   + 2 * BT;        // [56]

    const int tid = threadIdx.x;
    const int rg  = tid >> 6;             // 0..6, 8 batch rows each
    const int cg  = tid & 63;             // 0..63, 2 channels each
    const int r0  = rg << 3;
    const int ch0 = cg << 1;
    const int b0  = blockIdx.x * BT;

    // ---- constants to registers ----
    u64 bzr[4];
    #pragma unroll
    for (int q = 0; q < 4; q++) bzr[q] = *reinterpret_cast<const u64*>(&bz[(q << 7) + ch0]);
    const u64 cb1r = *reinterpret_cast<const u64*>(&b1[ch0]);
    const u64 cb2r = *reinterpret_cast<const u64*>(&b2[ch0]);
    const float wo0 = Wout[ch0], wo1 = Wout[ch0 + 1];
    const float boutv = bout[0];

    // ---- input feature pointer (all 448 threads: 8 feats x 56 rows) ----
    const int lf = tid / BT, lr = tid - lf * BT;
    int lb = b0 + lr; if (lb > B_TOT - 1) lb = B_TOT - 1;
    const float* fptr;
    if      (lf == 0) fptr = x0; else if (lf == 1) fptr = x1;
    else if (lf == 2) fptr = x2; else if (lf == 3) fptr = x3;
    else if (lf == 4) fptr = x4; else if (lf == 5) fptr = x5;
    else if (lf == 6) fptr = x6; else              fptr = irr;
    fptr = (lf < 7) ? (fptr + lb * T_STEPS) : (fptr + lb * WARM);
    const int tmax = (lf < 7) ? (T_STEPS - 1) : (WARM - 1);
    float vin = __ldg(fptr);              // input for t=0

    // ---- init h = 0 ----
    for (int i = tid; i < 128 * RSTR; i += NT) hbuf[i] = 0.f;

    // ---- prologue: stage z chunk 0 (Wh rows 0..7) into wsm[0] ----
    {
        const float4* s4 = reinterpret_cast<const float4*>(Wh);
        float4* d4 = reinterpret_cast<float4*>(wsm);
        d4[tid] = s4[tid];
        d4[tid + 448] = s4[tid + 448];
        if (tid < 128) d4[tid + 896] = s4[tid + 896];
    }
    int pb = 0;

    u64 cst[4][2];
    #pragma unroll
    for (int rp = 0; rp < 4; rp++){ cst[rp][0] = 0ull; cst[rp][1] = 0ull; }

    __syncthreads();

    for (int t = 0; t < T_STEPS; ++t){
        // ---- stage this step's input into hbuf rows 128..135; prefetch next ----
        {
            float v = (lf < 7 || t < WARM) ? vin : predb[lr];
            hbuf[(128 + lf) * RSTR + lr] = v;
            int tn = (t + 1 < tmax) ? (t + 1) : tmax;
            vin = __ldg(fptr + tn);
        }

        // ================= z = [h, inp] @ [Wh; Wi] + b =================
        u64 acc[4][8];
        #pragma unroll
        for (int q = 0; q < 4; q++){
            float bq0, bq1; unpack2(bzr[q], bq0, bq1);
            u64 p0 = pack2(bq0, bq0), p1 = pack2(bq1, bq1);
            #pragma unroll
            for (int rp = 0; rp < 4; rp++){ acc[rp][(q<<1)] = p0; acc[rp][(q<<1)+1] = p1; }
        }

        for (int c = 0; c <= 16; ++c){
            // prefetch next chunk (z c+1, then Wi, then W1 chunk 0)
            const float* src = (c < 15) ? (Wh + (c + 1) * 4096) : ((c == 15) ? Wi : W1);
            const float4* s4 = reinterpret_cast<const float4*>(src);
            float4 v0 = s4[tid];
            float4 v1 = s4[tid + 448];
            float4 v2; if (tid < 128) v2 = s4[tid + 896];

            const float* wb = wsm + (pb << 12);
            const int k0 = c << 3;
            #pragma unroll
            for (int kk = 0; kk < 8; kk++){
                const u64* h64 = reinterpret_cast<const u64*>(hbuf + (k0 + kk) * RSTR + r0);
                u64 hp0 = h64[0], hp1 = h64[1], hp2 = h64[2], hp3 = h64[3];
                #pragma unroll
                for (int q = 0; q < 4; q++){
                    u64 wp = *reinterpret_cast<const u64*>(&wb[(kk << 9) + (q << 7) + ch0]);
                    float w0, w1; unpack2(wp, w0, w1);
                    u64 w00 = pack2(w0, w0), w11 = pack2(w1, w1);
                    acc[0][(q<<1)]   = fma2(hp0, w00, acc[0][(q<<1)]);
                    acc[1][(q<<1)]   = fma2(hp1, w00, acc[1][(q<<1)]);
                    acc[2][(q<<1)]   = fma2(hp2, w00, acc[2][(q<<1)]);
                    acc[3][(q<<1)]   = fma2(hp3, w00, acc[3][(q<<1)]);
                    acc[0][(q<<1)+1] = fma2(hp0, w11, acc[0][(q<<1)+1]);
                    acc[1][(q<<1)+1] = fma2(hp1, w11, acc[1][(q<<1)+1]);
                    acc[2][(q<<1)+1] = fma2(hp2, w11, acc[2][(q<<1)+1]);
                    acc[3][(q<<1)+1] = fma2(hp3, w11, acc[3][(q<<1)+1]);
                }
            }
            float4* d4 = reinterpret_cast<float4*>(wsm + ((pb ^ 1) << 12));
            d4[tid] = v0;
            d4[tid + 448] = v1;
            if (tid < 128) d4[tid + 896] = v2;
            __syncthreads();
            pb ^= 1;
        }

        // ================= gates; c-state in regs; write new h =================
        #pragma unroll
        for (int rp = 0; rp < 4; rp++)
            #pragma unroll
            for (int d = 0; d < 2; d++){
                float zi0,zi1,zf0,zf1,zg0,zg1,zo0,zo1,c0,c1;
                unpack2(acc[rp][0+d], zi0, zi1);
                unpack2(acc[rp][2+d], zf0, zf1);
                unpack2(acc[rp][4+d], zg0, zg1);
                unpack2(acc[rp][6+d], zo0, zo1);
                unpack2(cst[rp][d], c0, c1);
                c0 = sig_(zf0)*c0 + sig_(zi0)*tanh_(zg0);
                c1 = sig_(zf1)*c1 + sig_(zi1)*tanh_(zg1);
                cst[rp][d] = pack2(c0, c1);
                float h0 = sig_(zo0)*tanh_(c0);
                float h1 = sig_(zo1)*tanh_(c1);
                *reinterpret_cast<u64*>(&hbuf[(ch0+d)*RSTR + r0 + (rp<<1)]) = pack2(h0, h1);
            }
        __syncthreads();

        // ================= m1 = relu(h @ W1 + b1) =================
        u64 a1[4][2];
        {
            float q0, q1; unpack2(cb1r, q0, q1);
            u64 p0 = pack2(q0,q0), p1 = pack2(q1,q1);
            #pragma unroll
            for (int rp = 0; rp < 4; rp++){ a1[rp][0] = p0; a1[rp][1] = p1; }
        }
        for (int c = 0; c < 4; ++c){
            const float* src = (c < 3) ? (W1 + (c + 1) * 4096) : W2;
            const float4* s4 = reinterpret_cast<const float4*>(src);
            float4 v0 = s4[tid];
            float4 v1 = s4[tid + 448];
            float4 v2; if (tid < 128) v2 = s4[tid + 896];

            const float* wb = wsm + (pb << 12);
            const int k0 = c << 5;
            #pragma unroll 8
            for (int kk = 0; kk < 32; kk++){
                const u64* h64 = reinterpret_cast<const u64*>(hbuf + (k0 + kk) * RSTR + r0);
                u64 hp0 = h64[0], hp1 = h64[1], hp2 = h64[2], hp3 = h64[3];
                u64 wp = *reinterpret_cast<const u64*>(&wb[(kk << 7) + ch0]);
                float w0, w1; unpack2(wp, w0, w1);
                u64 w00 = pack2(w0, w0), w11 = pack2(w1, w1);
                a1[0][0] = fma2(hp0, w00, a1[0][0]);
                a1[1][0] = fma2(hp1, w00, a1[1][0]);
                a1[2][0] = fma2(hp2, w00, a1[2][0]);
                a1[3][0] = fma2(hp3, w00, a1[3][0]);
                a1[0][1] = fma2(hp0, w11, a1[0][1]);
                a1[1][1] = fma2(hp1, w11, a1[1][1]);
                a1[2][1] = fma2(hp2, w11, a1[2][1]);
                a1[3][1] = fma2(hp3, w11, a1[3][1]);
            }
            float4* d4 = reinterpret_cast<float4*>(wsm + ((pb ^ 1) << 12));
            d4[tid] = v0;
            d4[tid + 448] = v1;
            if (tid < 128) d4[tid + 896] = v2;
            __syncthreads();
            pb ^= 1;
        }
        #pragma unroll
        for (int rp = 0; rp < 4; rp++)
            #pragma unroll
            for (int d = 0; d < 2; d++){
                float v0, v1; unpack2(a1[rp][d], v0, v1);
                *reinterpret_cast<u64*>(&m1buf[(ch0+d)*RSTR + r0 + (rp<<1)]) =
                    pack2(fmaxf(v0, 0.f), fmaxf(v1, 0.f));
            }
        __syncthreads();

        // ================= m2 = relu(m1 @ W2 + b2) =================
        u64 a2[4][2];
        {
            float q0, q1; unpack2(cb2r, q0, q1);
            u64 p0 = pack2(q0,q0), p1 = pack2(q1,q1);
            #pragma unroll
            for (int rp = 0; rp < 4; rp++){ a2[rp][0] = p0; a2[rp][1] = p1; }
        }
        for (int c = 0; c < 4; ++c){
            const float* src = (c < 3) ? (W2 + (c + 1) * 4096) : Wh;  // last: next step z c0
            const float4* s4 = reinterpret_cast<const float4*>(src);
            float4 v0 = s4[tid];
            float4 v1 = s4[tid + 448];
            float4 v2; if (tid < 128) v2 = s4[tid + 896];

            const float* wb = wsm + (pb << 12);
            const int k0 = c << 5;
            #pragma unroll 8
            for (int kk = 0; kk < 32; kk++){
                const u64* h64 = reinterpret_cast<const u64*>(m1buf + (k0 + kk) * RSTR + r0);
                u64 hp0 = h64[0], hp1 = h64[1], hp2 = h64[2], hp3 = h64[3];
                u64 wp = *reinterpret_cast<const u64*>(&wb[(kk << 7) + ch0]);
                float w0, w1; unpack2(wp, w0, w1);
                u64 w00 = pack2(w0, w0), w11 = pack2(w1, w1);
                a2[0][0] = fma2(hp0, w00, a2[0][0]);
                a2[1][0] = fma2(hp1, w00, a2[1][0]);
                a2[2][0] = fma2(hp2, w00, a2[2][0]);
                a2[3][0] = fma2(hp3, w00, a2[3][0]);
                a2[0][1] = fma2(hp0, w11, a2[0][1]);
                a2[1][1] = fma2(hp1, w11, a2[1][1]);
                a2[2][1] = fma2(hp2, w11, a2[2][1]);
                a2[3][1] = fma2(hp3, w11, a2[3][1]);
            }
            float4* d4 = reinterpret_cast<float4*>(wsm + ((pb ^ 1) << 12));
            d4[tid] = v0;
            d4[tid + 448] = v1;
            if (tid < 128) d4[tid + 896] = v2;
            __syncthreads();
            pb ^= 1;
        }

        // ---- out-projection in registers + warp shuffle reduce ----
        float p[8];
        #pragma unroll
        for (int rp = 0; rp < 4; rp++){
            float v0a, v0b, v1a, v1b;
            unpack2(a2[rp][0], v0a, v0b);   // channel ch0, rows (2rp, 2rp+1)
            unpack2(a2[rp][1], v1a, v1b);   // channel ch0+1
            p[(rp<<1)  ] = fmaxf(v0a, 0.f) * wo0 + fmaxf(v1a, 0.f) * wo1;
            p[(rp<<1)+1] = fmaxf(v0b, 0.f) * wo0 + fmaxf(v1b, 0.f) * wo1;
        }
        #pragma unroll
        for (int j = 0; j < 8; j++)
            #pragma unroll
            for (int off = 16; off; off >>= 1)
                p[j] += __shfl_xor_sync(0xffffffffu, p[j], off);
        if ((tid & 31) == 0){
            int half = (tid >> 5) & 1;
            #pragma unroll
            for (int j = 0; j < 8; j++) red[half * BT + r0 + j] = p[j];
        }
        __syncthreads();
        if (tid < BT){
            float s = boutv + red[tid] + red[BT + tid];
            predb[tid] = s;
            int bb = b0 + tid;
            if (bb < B_TOT) out[bb * T_STEPS + t] = s;
        }
        __syncthreads();
    }
}

extern "C" void kernel_launch(void* const* d_in, const int* in_sizes, int n_in,
                              void* d_out, int out_size)
{
    (void)in_sizes; (void)n_in; (void)out_size;
    cudaFuncSetAttribute(fused_lstm_kernel, cudaFuncAttributeMaxDynamicSharedMemorySize, SMEM_BYTES);
    int grid = (B_TOT + BT - 1) / BT; // 147
    fused_lstm_kernel<<<grid, NT, SMEM_BYTES>>>(
        (const float*)d_in[8],  (const float*)d_in[9],  (const float*)d_in[10],
        (const float*)d_in[11], (const float*)d_in[12], (const float*)d_in[13],
        (const float*)d_in[14], (const float*)d_in[15],
        (const float*)d_in[16], (const float*)d_in[17], (const float*)d_in[18],
        (const float*)d_in[19], (const float*)d_in[20], (const float*)d_in[21],
        (const float*)d_in[22], (const float*)d_in[23], (const float*)d_in[24],
        (float*)d_out);
}